// round 3
// baseline (speedup 1.0000x reference)
#include <cuda_runtime.h>
#include <math.h>

#define C      256
#define RBF    64
#define EPB    64     // edges per block (stage A)
#define NPB    64     // nodes per block (stage B)
#define N_MAX  50000

// Scratch for segment-summed messages (no cudaMalloc allowed).
__device__ float g_agg[(size_t)N_MAX * C];

// ---------------------------------------------------------------------------
// Zero the aggregation buffer (graph replays reuse it).
// ---------------------------------------------------------------------------
__global__ void zero_agg_kernel(int total4) {
    float4 z = make_float4(0.f, 0.f, 0.f, 0.f);
    float4* p = (float4*)g_agg;
    for (int i = blockIdx.x * blockDim.x + threadIdx.x; i < total4;
         i += gridDim.x * blockDim.x)
        p[i] = z;
}

// ---------------------------------------------------------------------------
// Stage A: per-edge  msg = embed[node_z[sender]] * ((ef @ W_dist + b) * cut)
// segment-summed into g_agg[receiver].  Receivers are sorted, so each thread
// keeps a running accumulator and only touches global atomics on run
// boundaries (~E/16 runs total).
// One block = 64 consecutive edges, 256 threads = one output channel each.
// W_dist column lives in 64 registers per thread.
// ---------------------------------------------------------------------------
__global__ __launch_bounds__(256) void edge_kernel(
    const int*   __restrict__ node_z,
    const int*   __restrict__ senders,
    const int*   __restrict__ receivers,
    const float* __restrict__ edge_weight,
    const float* __restrict__ edge_feats,
    const float* __restrict__ embed_table,
    const float* __restrict__ W_dist,
    const float* __restrict__ b_dist,
    int E)
{
    __shared__ float ef_sh[EPB][RBF];   // 16 KB, contiguous copy of the chunk
    __shared__ int   sp_sh[EPB];
    __shared__ int   r_sh[EPB];
    __shared__ float cut_sh[EPB];

    const int e0  = blockIdx.x * EPB;
    const int tid = threadIdx.x;
    const int ne  = min(EPB, E - e0);

    // per-edge metadata (one thread per edge)
    if (tid < ne) {
        int e = e0 + tid;
        int s = senders[e];
        sp_sh[tid] = node_z[s];
        r_sh[tid]  = receivers[e];
        float w = edge_weight[e];
        float cut = 0.5f * (cosf(w * 0.62831853071795864769f) + 1.0f); // pi/5
        cut_sh[tid] = (w < 5.0f) ? cut : 0.0f;
    }
    // edge_feats chunk is fully contiguous in gmem -> straight float4 copy
    {
        const float4* src = (const float4*)(edge_feats + (size_t)e0 * RBF);
        float4* dst = (float4*)&ef_sh[0][0];
        int n4 = ne * (RBF / 4);
        for (int i = tid; i < n4; i += 256) dst[i] = src[i];
    }
    __syncthreads();

    const int c = tid;
    float Wc[RBF];
    #pragma unroll
    for (int k = 0; k < RBF; k++) Wc[k] = W_dist[k * C + c];   // coalesced
    const float bd = b_dist[c];

    float acc  = 0.f;
    int cur_r  = -1;

    for (int el = 0; el < ne; el++) {
        int r = r_sh[el];                      // uniform across block
        if (r != cur_r) {
            if (cur_r >= 0) atomicAdd(&g_agg[(size_t)cur_r * C + c], acc);
            acc = 0.f;
            cur_r = r;
        }
        const float4* efp = (const float4*)&ef_sh[el][0];  // broadcast LDS
        float p0 = 0.f, p1 = 0.f, p2 = 0.f, p3 = 0.f;
        #pragma unroll
        for (int k4 = 0; k4 < RBF / 4; k4++) {
            float4 v = efp[k4];
            p0 = fmaf(v.x, Wc[4 * k4 + 0], p0);
            p1 = fmaf(v.y, Wc[4 * k4 + 1], p1);
            p2 = fmaf(v.z, Wc[4 * k4 + 2], p2);
            p3 = fmaf(v.w, Wc[4 * k4 + 3], p3);
        }
        float proj = ((p0 + p1) + (p2 + p3)) + bd;
        float xj   = embed_table[sp_sh[el] * C + c];       // 100x256 table, L1-hot
        acc = fmaf(xj * cut_sh[el], proj, acc);
    }
    if (cur_r >= 0) atomicAdd(&g_agg[(size_t)cur_r * C + c], acc);
}

// ---------------------------------------------------------------------------
// Stage B: out = concat(node_feats, agg) @ W_comb + b_comb
// One block = 64 nodes x 256 channels, acc[64] in registers.
// K = 512 processed in 8 shared tiles of 64 (first 4 from node_feats,
// last 4 from g_agg -> concat never materialized).
// ---------------------------------------------------------------------------
__global__ __launch_bounds__(256) void node_kernel(
    const float* __restrict__ node_feats,
    const float* __restrict__ W_comb,
    const float* __restrict__ b_comb,
    float*       __restrict__ out,
    int n_nodes)
{
    __shared__ float x_sh[NPB][64];   // 16 KB tile

    const int n0  = blockIdx.x * NPB;
    const int tid = threadIdx.x;
    const int c   = tid;
    const int nn  = min(NPB, n_nodes - n0);

    float acc[NPB];
    #pragma unroll
    for (int i = 0; i < NPB; i++) acc[i] = 0.f;

    for (int kb = 0; kb < 8; kb++) {
        const float* srcbase = (kb < 4) ? node_feats : g_agg;
        const int    off     = (kb & 3) * 64;

        // load the 64-wide K-slice for up to 64 rows (float4, coalesced)
        for (int idx = tid; idx < NPB * 16; idx += 256) {
            int row = idx >> 4;
            int j   = idx & 15;
            float4 v = (row < nn)
                ? ((const float4*)(srcbase + (size_t)(n0 + row) * C + off))[j]
                : make_float4(0.f, 0.f, 0.f, 0.f);
            ((float4*)&x_sh[row][0])[j] = v;
        }
        __syncthreads();

        const float* Wk = W_comb + (size_t)(kb * 64) * C + c;
        for (int k4 = 0; k4 < 16; k4++) {
            float w0 = Wk[(4 * k4 + 0) * C];
            float w1 = Wk[(4 * k4 + 1) * C];
            float w2 = Wk[(4 * k4 + 2) * C];
            float w3 = Wk[(4 * k4 + 3) * C];
            #pragma unroll
            for (int i = 0; i < NPB; i++) {
                float4 xv = ((const float4*)&x_sh[i][0])[k4];  // broadcast
                acc[i] = fmaf(xv.x, w0, acc[i]);
                acc[i] = fmaf(xv.y, w1, acc[i]);
                acc[i] = fmaf(xv.z, w2, acc[i]);
                acc[i] = fmaf(xv.w, w3, acc[i]);
            }
        }
        __syncthreads();
    }

    const float b = b_comb[c];
    for (int i = 0; i < nn; i++)
        out[(size_t)(n0 + i) * C + c] = acc[i] + b;   // coalesced across threads
}

// ---------------------------------------------------------------------------
extern "C" void kernel_launch(void* const* d_in, const int* in_sizes, int n_in,
                              void* d_out, int out_size)
{
    const int*   node_z      = (const int*)  d_in[0];
    const float* node_feats  = (const float*)d_in[1];
    const int*   senders     = (const int*)  d_in[2];
    const int*   receivers   = (const int*)  d_in[3];
    const float* edge_weight = (const float*)d_in[4];
    const float* edge_feats  = (const float*)d_in[5];
    const float* embed_table = (const float*)d_in[6];
    const float* W_dist      = (const float*)d_in[7];
    const float* b_dist      = (const float*)d_in[8];
    const float* W_comb      = (const float*)d_in[9];
    const float* b_comb      = (const float*)d_in[10];
    float* out = (float*)d_out;

    const int n_nodes = in_sizes[0];   // 50000
    const int E       = in_sizes[2];   // 800000

    zero_agg_kernel<<<2048, 256>>>(n_nodes * C / 4);

    edge_kernel<<<(E + EPB - 1) / EPB, 256>>>(
        node_z, senders, receivers, edge_weight, edge_feats,
        embed_table, W_dist, b_dist, E);

    node_kernel<<<(n_nodes + NPB - 1) / NPB, 256>>>(
        node_feats, W_comb, b_comb, out, n_nodes);
}

// round 4
// speedup vs baseline: 1.3325x; 1.3325x over previous
#include <cuda_runtime.h>
#include <math.h>

#define C      256
#define RBF    64
#define EPB    128    // edges per block (64 packed pairs)
#define NPB    64     // nodes per block (32 packed pairs)
#define N_MAX  50000

// Scratch for segment-summed messages (no cudaMalloc allowed).
__device__ float g_agg[(size_t)N_MAX * C];

typedef unsigned long long u64t;

// ---- packed f32x2 helpers (sm_100+; ptxas never emits these from C++) ----
__device__ __forceinline__ u64t pack2(float lo, float hi) {
    u64t d; asm("mov.b64 %0, {%1, %2};" : "=l"(d) : "f"(lo), "f"(hi)); return d;
}
__device__ __forceinline__ void unpack2(u64t v, float& lo, float& hi) {
    asm("mov.b64 {%0, %1}, %2;" : "=f"(lo), "=f"(hi) : "l"(v));
}
__device__ __forceinline__ u64t ffma2(u64t a, u64t b, u64t c) {
    u64t d; asm("fma.rn.f32x2 %0, %1, %2, %3;" : "=l"(d) : "l"(a), "l"(b), "l"(c));
    return d;
}
__device__ __forceinline__ u64t fadd2(u64t a, u64t b) {
    u64t d; asm("add.rn.f32x2 %0, %1, %2;" : "=l"(d) : "l"(a), "l"(b)); return d;
}

// ---------------------------------------------------------------------------
__global__ void zero_agg_kernel(int total4) {
    float4 z = make_float4(0.f, 0.f, 0.f, 0.f);
    float4* p = (float4*)g_agg;
    for (int i = blockIdx.x * blockDim.x + threadIdx.x; i < total4;
         i += gridDim.x * blockDim.x)
        p[i] = z;
}

// ---------------------------------------------------------------------------
// Stage A:  agg[r] += embed[z[sender]] * ((ef @ W_dist)*cut + cut*b)
// Edges processed in packed pairs via fma.rn.f32x2.
// Shared tile holds y = cut*ef pair-interleaved: [pair][k][2] so that one
// LDS.128 yields two packed (e0,e1) k-operands.  W_dist column pre-splatted
// into 64 b64 registers.  Sorted receivers -> run accumulation + rare atomics.
// ---------------------------------------------------------------------------
__global__ __launch_bounds__(256) void edge_kernel(
    const int*   __restrict__ node_z,
    const int*   __restrict__ senders,
    const int*   __restrict__ receivers,
    const float* __restrict__ edge_weight,
    const float* __restrict__ edge_feats,
    const float* __restrict__ embed_table,
    const float* __restrict__ W_dist,
    const float* __restrict__ b_dist,
    int E)
{
    __shared__ float ef2[EPB / 2][RBF][2];   // 32 KB: y = cut*ef, pair-interleaved
    __shared__ int   sp_sh[EPB];
    __shared__ int   r_sh[EPB];
    __shared__ float cut_sh[EPB];

    const int e0  = blockIdx.x * EPB;
    const int tid = threadIdx.x;
    const int ne  = min(EPB, E - e0);

    if (tid < EPB) {
        if (tid < ne) {
            int e = e0 + tid;
            sp_sh[tid] = node_z[senders[e]];
            r_sh[tid]  = receivers[e];
            float w = edge_weight[e];
            float cut = 0.5f * (cosf(w * 0.62831853071795864769f) + 1.0f); // pi/5
            cut_sh[tid] = (w < 5.0f) ? cut : 0.0f;
        } else {               // pad edges: contribute exactly zero
            sp_sh[tid]  = 0;
            r_sh[tid]   = receivers[e0 + ne - 1];
            cut_sh[tid] = 0.0f;
        }
    }
    __syncthreads();

    // stage y = cut*ef (pad rows zeroed)
    {
        const float4* src = (const float4*)(edge_feats + (size_t)e0 * RBF);
        for (int idx = tid; idx < EPB * 16; idx += 256) {
            int e = idx >> 4, j = idx & 15;
            float4 v = (idx < ne * 16) ? src[idx] : make_float4(0.f, 0.f, 0.f, 0.f);
            float ct = cut_sh[e];
            int p = e >> 1, h = e & 1, k = 4 * j;
            ef2[p][k + 0][h] = v.x * ct;
            ef2[p][k + 1][h] = v.y * ct;
            ef2[p][k + 2][h] = v.z * ct;
            ef2[p][k + 3][h] = v.w * ct;
        }
    }
    __syncthreads();

    const int c = tid;
    u64t W2[RBF];                              // splat(W_dist[k,c]) — 128 regs
    #pragma unroll
    for (int k = 0; k < RBF; k++) {
        float w = W_dist[k * C + c];           // coalesced
        W2[k] = pack2(w, w);
    }
    const float bd = b_dist[c];

    float acc  = 0.f;
    int   cur_r = -1;

    for (int p = 0; p < EPB / 2; p++) {
        const ulonglong2* yp = (const ulonglong2*)&ef2[p][0][0];  // broadcast LDS
        u64t a0 = 0, a1 = 0, a2 = 0, a3 = 0;
        #pragma unroll
        for (int k8 = 0; k8 < RBF / 8; k8++) {
            ulonglong2 q0 = yp[4 * k8 + 0];
            ulonglong2 q1 = yp[4 * k8 + 1];
            ulonglong2 q2 = yp[4 * k8 + 2];
            ulonglong2 q3 = yp[4 * k8 + 3];
            a0 = ffma2(q0.x, W2[8 * k8 + 0], a0);
            a1 = ffma2(q0.y, W2[8 * k8 + 1], a1);
            a2 = ffma2(q1.x, W2[8 * k8 + 2], a2);
            a3 = ffma2(q1.y, W2[8 * k8 + 3], a3);
            a0 = ffma2(q2.x, W2[8 * k8 + 4], a0);
            a1 = ffma2(q2.y, W2[8 * k8 + 5], a1);
            a2 = ffma2(q3.x, W2[8 * k8 + 6], a2);
            a3 = ffma2(q3.y, W2[8 * k8 + 7], a3);
        }
        u64t P = fadd2(fadd2(a0, a1), fadd2(a2, a3));
        float pr0, pr1;
        unpack2(P, pr0, pr1);

        const int e_lo = 2 * p, e_hi = 2 * p + 1;
        {   // edge e_lo
            int r = r_sh[e_lo];
            if (r != cur_r) {
                if (cur_r >= 0) atomicAdd(&g_agg[(size_t)cur_r * C + c], acc);
                acc = 0.f; cur_r = r;
            }
            float xj = embed_table[sp_sh[e_lo] * C + c];     // 100x256, cache-hot
            acc = fmaf(xj, fmaf(cut_sh[e_lo], bd, pr0), acc);
        }
        {   // edge e_hi
            int r = r_sh[e_hi];
            if (r != cur_r) {
                if (cur_r >= 0) atomicAdd(&g_agg[(size_t)cur_r * C + c], acc);
                acc = 0.f; cur_r = r;
            }
            float xj = embed_table[sp_sh[e_hi] * C + c];
            acc = fmaf(xj, fmaf(cut_sh[e_hi], bd, pr1), acc);
        }
    }
    if (cur_r >= 0) atomicAdd(&g_agg[(size_t)cur_r * C + c], acc);
}

// ---------------------------------------------------------------------------
// Stage B: out = concat(node_feats, agg) @ W_comb + b_comb
// Node pairs packed via fma.rn.f32x2.  Transposed shared tile [k][pair][2]
// so one LDS.128 yields two packed node-pair operands for the same k.
// K=512 done in 8 tiles of 64, alternating node_feats / g_agg (concat never
// materialized).
// ---------------------------------------------------------------------------
__global__ __launch_bounds__(256) void node_kernel(
    const float* __restrict__ node_feats,
    const float* __restrict__ W_comb,
    const float* __restrict__ b_comb,
    float*       __restrict__ out,
    int n_nodes)
{
    __shared__ float x2[64][NPB / 2][2];   // 16 KB, [k][pair][half]

    const int n0  = blockIdx.x * NPB;
    const int tid = threadIdx.x;
    const int c   = tid;
    const int nn  = min(NPB, n_nodes - n0);

    u64t acc2[NPB / 2];
    #pragma unroll
    for (int i = 0; i < NPB / 2; i++) acc2[i] = 0ull;

    for (int kb = 0; kb < 8; kb++) {
        const float* srcbase = (kb < 4) ? node_feats : g_agg;
        const int    off     = (kb & 3) * 64;

        for (int idx = tid; idx < NPB * 16; idx += 256) {
            int row = idx >> 4, j = idx & 15;
            float4 v = (row < nn)
                ? ((const float4*)(srcbase + (size_t)(n0 + row) * C + off))[j]
                : make_float4(0.f, 0.f, 0.f, 0.f);
            int p = row >> 1, h = row & 1, k = 4 * j;
            x2[k + 0][p][h] = v.x;
            x2[k + 1][p][h] = v.y;
            x2[k + 2][p][h] = v.z;
            x2[k + 3][p][h] = v.w;
        }
        __syncthreads();

        const float* Wk = W_comb + (size_t)(kb * 64) * C + c;
        #pragma unroll 4
        for (int k = 0; k < 64; k++) {
            float w  = Wk[(size_t)k * C];                  // coalesced LDG
            u64t  ws = pack2(w, w);
            const ulonglong2* xp = (const ulonglong2*)&x2[k][0][0];  // broadcast
            #pragma unroll
            for (int p2 = 0; p2 < 16; p2++) {
                ulonglong2 q = xp[p2];
                acc2[2 * p2 + 0] = ffma2(q.x, ws, acc2[2 * p2 + 0]);
                acc2[2 * p2 + 1] = ffma2(q.y, ws, acc2[2 * p2 + 1]);
            }
        }
        __syncthreads();
    }

    const float b = b_comb[c];
    for (int p = 0; p < NPB / 2; p++) {
        float lo, hi;
        unpack2(acc2[p], lo, hi);
        int r0 = 2 * p, r1 = 2 * p + 1;
        if (r0 < nn) out[(size_t)(n0 + r0) * C + c] = lo + b;
        if (r1 < nn) out[(size_t)(n0 + r1) * C + c] = hi + b;
    }
}

// ---------------------------------------------------------------------------
extern "C" void kernel_launch(void* const* d_in, const int* in_sizes, int n_in,
                              void* d_out, int out_size)
{
    const int*   node_z      = (const int*)  d_in[0];
    const float* node_feats  = (const float*)d_in[1];
    const int*   senders     = (const int*)  d_in[2];
    const int*   receivers   = (const int*)  d_in[3];
    const float* edge_weight = (const float*)d_in[4];
    const float* edge_feats  = (const float*)d_in[5];
    const float* embed_table = (const float*)d_in[6];
    const float* b_dist_W    = (const float*)d_in[7];   // W_dist
    const float* b_dist      = (const float*)d_in[8];
    const float* W_comb      = (const float*)d_in[9];
    const float* b_comb      = (const float*)d_in[10];
    float* out = (float*)d_out;

    const int n_nodes = in_sizes[0];   // 50000
    const int E       = in_sizes[2];   // 800000

    zero_agg_kernel<<<2048, 256>>>(n_nodes * C / 4);

    edge_kernel<<<(E + EPB - 1) / EPB, 256>>>(
        node_z, senders, receivers, edge_weight, edge_feats,
        embed_table, b_dist_W, b_dist, E);

    node_kernel<<<(n_nodes + NPB - 1) / NPB, 256>>>(
        node_feats, W_comb, b_comb, out, n_nodes);
}